// round 11
// baseline (speedup 1.0000x reference)
#include <cuda_runtime.h>

#define FULLMASK 0xffffffffu
#define C_IN 32
#define C_OUT 64
#define K_TAPS 8
#define NMAX 2001024
#define BSHIFT 10                    // 1024 output rows per bucket
#define BROWS (1 << BSHIFT)
#define NBMAX ((NMAX >> BSHIFT) + 2)
#define NBINSMAX (NBMAX * 8)
#define BATCH 4
#define IDXMASK 0x1FFFFF

// ---------------- device scratch ----------------
__device__ float g_sum[C_IN];
__device__ float g_sq[C_IN];
__device__ float g_scale[C_IN];
__device__ float g_shift[C_IN];
__device__ int   g_hist2[NBINSMAX];
__device__ int   g_base2[NBINSMAX + 1];
__device__ int   g_cur2[NBINSMAX];
__device__ int   g_perm[NMAX];

// ---------------- PTX helpers ----------------
__device__ __forceinline__ unsigned long long fma2(unsigned long long a,
                                                   unsigned long long b,
                                                   unsigned long long c) {
    unsigned long long d;
    asm("fma.rn.f32x2 %0, %1, %2, %3;" : "=l"(d) : "l"(a), "l"(b), "l"(c));
    return d;
}
__device__ __forceinline__ unsigned long long add2(unsigned long long a,
                                                   unsigned long long b) {
    unsigned long long d;
    asm("add.rn.f32x2 %0, %1, %2;" : "=l"(d) : "l"(a), "l"(b));
    return d;
}
__device__ __forceinline__ unsigned long long pk(float lo, float hi) {
    unsigned long long d;
    asm("mov.b64 %0, {%1, %2};" : "=l"(d) : "f"(lo), "f"(hi));
    return d;
}
__device__ __forceinline__ void upk(unsigned long long v, float& lo, float& hi) {
    asm("mov.b64 {%0, %1}, %2;" : "=f"(lo), "=f"(hi) : "l"(v));
}
__device__ __forceinline__ void red_add_f32(float* p, float v) {
    asm volatile("red.global.add.f32 [%0], %1;" :: "l"(p), "f"(v) : "memory");
}
__device__ __forceinline__ void bar_named(int id, int cnt) {
    asm volatile("bar.sync %0, %1;" :: "r"(id), "r"(cnt) : "memory");
}

// ---------------- BN stats + 2-D (bucket,tap) histogram ----------------
// g_hist2 / g_sum / g_sq zero on entry (zero-init at load; re-zeroed by
// k_scanmid each call -> replay-safe).
__global__ void __launch_bounds__(256) k_pre(
    const float4* __restrict__ f4, long nf4,
    const int4* __restrict__ off4, const int4* __restrict__ oix4,
    int nq, int n) {
    long tid = blockIdx.x * (long)blockDim.x + threadIdx.x;
    long S = (long)gridDim.x * blockDim.x;   // 4*S % 32 == 0

    float s0 = 0, s1 = 0, s2 = 0, s3 = 0;
    float q0 = 0, q1 = 0, q2 = 0, q3 = 0;
    for (long i = tid; i < nf4; i += S) {
        float4 v = f4[i];
        s0 += v.x; q0 = fmaf(v.x, v.x, q0);
        s1 += v.y; q1 = fmaf(v.y, v.y, q1);
        s2 += v.z; q2 = fmaf(v.z, v.z, q2);
        s3 += v.w; q3 = fmaf(v.w, v.w, q3);
    }
    int c0 = (int)((tid * 4) & 31);

    __shared__ float ss[C_IN], sq[C_IN];
    int t = threadIdx.x;
    if (t < C_IN) { ss[t] = 0.f; sq[t] = 0.f; }
    __syncthreads();
    atomicAdd(&ss[c0 + 0], s0); atomicAdd(&sq[c0 + 0], q0);
    atomicAdd(&ss[c0 + 1], s1); atomicAdd(&sq[c0 + 1], q1);
    atomicAdd(&ss[c0 + 2], s2); atomicAdd(&sq[c0 + 2], q2);
    atomicAdd(&ss[c0 + 3], s3); atomicAdd(&sq[c0 + 3], q3);

    for (long i = tid; i < nq; i += S) {
        int4 o = off4[i];
        int4 r = oix4[i];
        atomicAdd(&g_hist2[((r.x >> BSHIFT) << 3) + (o.x & 7)], 1);
        atomicAdd(&g_hist2[((r.y >> BSHIFT) << 3) + (o.y & 7)], 1);
        atomicAdd(&g_hist2[((r.z >> BSHIFT) << 3) + (o.z & 7)], 1);
        atomicAdd(&g_hist2[((r.w >> BSHIFT) << 3) + (o.w & 7)], 1);
    }
    if (blockIdx.x == 0 && t < (n & 3)) {
        const int* off = (const int*)off4;
        const int* oix = (const int*)oix4;
        int e = (n & ~3) + t;
        atomicAdd(&g_hist2[((oix[e] >> BSHIFT) << 3) + (off[e] & 7)], 1);
    }
    __syncthreads();
    if (t < C_IN) {
        atomicAdd(&g_sum[t], ss[t]);
        atomicAdd(&g_sq[t], sq[t]);
    }
}

// ---------------- single-block: BN finalize + full bin scan + resets ----------------
__global__ void __launch_bounds__(1024) k_scanmid(
    const float* __restrict__ gamma, const float* __restrict__ beta,
    float inv_n, int nbins) {
    __shared__ int wtot[32];
    int t = threadIdx.x;
    int lane = t & 31, wid = t >> 5;

    if (t < C_IN) {
        float mean = g_sum[t] * inv_n;
        float var  = g_sq[t] * inv_n - mean * mean;
        float sc   = gamma[t] * rsqrtf(var + 1e-5f);
        g_scale[t] = sc;
        g_shift[t] = beta[t] - mean * sc;
        g_sum[t] = 0.f;
        g_sq[t]  = 0.f;
    }

    int b0 = t << 4;
    int h[16];
#pragma unroll
    for (int k = 0; k < 16; k++) {
        int b = b0 + k;
        h[k] = (b < nbins) ? g_hist2[b] : 0;
    }
    int s = 0;
#pragma unroll
    for (int k = 0; k < 16; k++) { int v = h[k]; h[k] = s; s += v; }

    int inc = s;
#pragma unroll
    for (int d = 1; d < 32; d <<= 1) {
        int u = __shfl_up_sync(FULLMASK, inc, d);
        if (lane >= d) inc += u;
    }
    if (lane == 31) wtot[wid] = inc;
    __syncthreads();
    if (wid == 0) {
        int x = wtot[lane];
#pragma unroll
        for (int d = 1; d < 32; d <<= 1) {
            int u = __shfl_up_sync(FULLMASK, x, d);
            if (lane >= d) x += u;
        }
        wtot[lane] = x;
    }
    __syncthreads();
    int base = (wid ? wtot[wid - 1] : 0) + inc - s;
#pragma unroll
    for (int k = 0; k < 16; k++) {
        int b = b0 + k;
        if (b < nbins) {
            int e = base + h[k];
            g_base2[b] = e;
            g_cur2[b] = e;
            g_hist2[b] = 0;
        }
    }
    if (t == 1023) g_base2[nbins] = base + s;
}

// ---------------- counting-sort scatter: packed (rowlow<<21 | idx) ----------------
__global__ void k_scat(const int4* __restrict__ off4,
                       const int4* __restrict__ oix4, int nq, int n) {
    int i = blockIdx.x * blockDim.x + threadIdx.x;
    int S = gridDim.x * blockDim.x;
    for (; i < nq; i += S) {
        int4 o = off4[i];
        int4 r = oix4[i];
        int base = i << 2;
        {
            int pos = atomicAdd(&g_cur2[((r.x >> BSHIFT) << 3) + (o.x & 7)], 1);
            g_perm[pos] = ((r.x & (BROWS - 1)) << 21) | (base + 0);
        }
        {
            int pos = atomicAdd(&g_cur2[((r.y >> BSHIFT) << 3) + (o.y & 7)], 1);
            g_perm[pos] = ((r.y & (BROWS - 1)) << 21) | (base + 1);
        }
        {
            int pos = atomicAdd(&g_cur2[((r.z >> BSHIFT) << 3) + (o.z & 7)], 1);
            g_perm[pos] = ((r.z & (BROWS - 1)) << 21) | (base + 2);
        }
        {
            int pos = atomicAdd(&g_cur2[((r.w >> BSHIFT) << 3) + (o.w & 7)], 1);
            g_perm[pos] = ((r.w & (BROWS - 1)) << 21) | (base + 3);
        }
    }
    if (blockIdx.x == 0 && threadIdx.x < (n & 3)) {
        const int* off = (const int*)off4;
        const int* oix = (const int*)oix4;
        int e = (n & ~3) + threadIdx.x;
        int row = oix[e];
        int pos = atomicAdd(&g_cur2[((row >> BSHIFT) << 3) + (off[e] & 7)], 1);
        g_perm[pos] = ((row & (BROWS - 1)) << 21) | e;
    }
}

// ---------------- main conv: 512-thr CTA per bucket, warp = (tap, col-half) ----------------
// Pair of warps {2*tap, 2*tap+1} share one staged copy of each point vector.
// Half-0 warp gathers + stages; both compute disjoint 32-column halves.
// Weights: one column per lane, channel-paired -> 16 u64 (32 regs).
__global__ void __launch_bounds__(512, 2)
k_conv(const float* __restrict__ f, const float* __restrict__ weight,
       float* __restrict__ out, int nb, int nrows) {
    __shared__ float sv[8][2][BATCH][C_IN];
    int lane = threadIdx.x & 31;
    int w = threadIdx.x >> 5;           // 0..15
    int tap = w >> 1;
    int half = w & 1;
    int col = (half << 5) + lane;
    bool stager = (half == 0);

    // channel-paired weights for this lane's single column
    unsigned long long wreg[16];
    {
        const float* wp = weight + (tap * C_IN) * C_OUT + col;
#pragma unroll
        for (int k = 0; k < 16; k++)
            wreg[k] = pk(wp[(2 * k) * C_OUT], wp[(2 * k + 1) * C_OUT]);
    }
    float sc = g_scale[lane];
    float sh = g_shift[lane];

    for (int b = blockIdx.x; b < nb; b += gridDim.x) {
        // zero this bucket's output region (stays dirty in L2 for the atomics)
        long r0 = (long)b << BSHIFT;
        long r1 = min((long)nrows, r0 + (long)BROWS);
        float4* oz = (float4*)(out + r0 * C_OUT);
        long n4 = (r1 - r0) * (C_OUT / 4);
        float4 z = make_float4(0.f, 0.f, 0.f, 0.f);
        for (long i = threadIdx.x; i < n4; i += 512) oz[i] = z;
        __syncthreads();

        int bin = (b << 3) + tap;
        int j = g_base2[bin];
        int j1 = g_base2[bin + 1];
        int rbase = b << BSHIFT;

        if (j < j1) {
            // ---- prologue: batch 0 words -> features -> rows; stage buf0 ----
            int m = min(BATCH, j1 - j);
            int rowc[BATCH], wn[BATCH];
            float x[BATCH];
#pragma unroll
            for (int t = 0; t < BATCH; t++)
                if (t < m) wn[t] = g_perm[j + t];           // words(0)
            if (stager) {
#pragma unroll
                for (int t = 0; t < BATCH; t++)
                    if (t < m) x[t] = f[((long)(wn[t] & IDXMASK) << 5) + lane];
            }
#pragma unroll
            for (int t = 0; t < BATCH; t++)
                if (t < m) rowc[t] = rbase + (wn[t] >> 21);
            int jn = j + m;
            int mn = min(BATCH, j1 - jn);
#pragma unroll
            for (int t = 0; t < BATCH; t++)
                if (t < mn) wn[t] = g_perm[jn + t];         // words(1)
            if (stager) {
#pragma unroll
                for (int t = 0; t < BATCH; t++)
                    if (t < m)
                        sv[tap][0][t][lane] = fmaxf(fmaf(x[t], sc, sh), 0.f);
            }

            int it = 0;
            while (j < j1) {
                bar_named(8 + tap, 64);   // batch k staged + buf (k+1)&1 free
                int buf = it & 1;

                // features(k+1) from words(k+1)
                if (stager) {
#pragma unroll
                    for (int t = 0; t < BATCH; t++)
                        if (t < mn) x[t] = f[((long)(wn[t] & IDXMASK) << 5) + lane];
                }
                // words(k+1) -> rows(k+1) in place
#pragma unroll
                for (int t = 0; t < BATCH; t++)
                    if (t < mn) wn[t] = rbase + (wn[t] >> 21);
                // words(k+2)
                int jn2 = jn + mn;
                int mn2 = min(BATCH, j1 - jn2);
                int wtmp[BATCH];
#pragma unroll
                for (int t = 0; t < BATCH; t++)
                    if (t < mn2) wtmp[t] = g_perm[jn2 + t];

                // compute + reduce batch k (16 fma2 over channel pairs, 1 col/lane)
#pragma unroll
                for (int t = 0; t < BATCH; t++)
                    if (t < m) {
                        const ulonglong2* vp =
                            (const ulonglong2*)&sv[tap][buf][t][0];
                        unsigned long long a0 = 0ull, a1 = 0ull;
#pragma unroll
                        for (int k = 0; k < 8; k++) {
                            ulonglong2 q = vp[k];
                            a0 = fma2(q.x, wreg[2 * k], a0);
                            a1 = fma2(q.y, wreg[2 * k + 1], a1);
                        }
                        unsigned long long a = add2(a0, a1);
                        float e, o;
                        upk(a, e, o);
                        red_add_f32(out + ((long)rowc[t] << 6) + col, e + o);
                    }

                // stage batch k+1 into the other buffer
                if (stager) {
#pragma unroll
                    for (int t = 0; t < BATCH; t++)
                        if (t < mn)
                            sv[tap][buf ^ 1][t][lane] =
                                fmaxf(fmaf(x[t], sc, sh), 0.f);
                }

                // rotate
#pragma unroll
                for (int t = 0; t < BATCH; t++) { rowc[t] = wn[t]; wn[t] = wtmp[t]; }
                j = jn; m = mn; jn = jn2; mn = mn2;
                it++;
            }
        }
        __syncthreads();   // all pairs done before next bucket's zeroing
    }
}

// ---------------- launch ----------------
extern "C" void kernel_launch(void* const* d_in, const int* in_sizes, int n_in,
                              void* d_out, int out_size) {
    const float* features = (const float*)d_in[0];
    const float* gamma    = (const float*)d_in[1];
    const float* beta     = (const float*)d_in[2];
    const float* weight   = (const float*)d_in[3];
    const int* out_index  = (const int*)d_in[4];
    const int* off_index  = (const int*)d_in[5];

    int n = in_sizes[0] / C_IN;
    int nq = n >> 2;
    int nrows = out_size / C_OUT;
    int nb = (nrows + BROWS - 1) >> BSHIFT;
    int nbins = nb * 8;

    k_pre<<<592, 256>>>((const float4*)features, (long)n * C_IN / 4,
                        (const int4*)off_index, (const int4*)out_index, nq, n);
    k_scanmid<<<1, 1024>>>(gamma, beta, 1.0f / (float)n, nbins);
    k_scat<<<592, 256>>>((const int4*)off_index, (const int4*)out_index, nq, n);
    k_conv<<<296, 512>>>(features, weight, (float*)d_out, nb, nrows);
}

// round 13
// speedup vs baseline: 1.6562x; 1.6562x over previous
#include <cuda_runtime.h>

#define FULLMASK 0xffffffffu
#define C_IN 32
#define C_OUT 64
#define K_TAPS 8
#define NMAX 2001024
#define BSHIFT 10                    // 1024 output rows per bucket
#define BROWS (1 << BSHIFT)
#define NBMAX ((NMAX >> BSHIFT) + 2)
#define NBINSMAX (NBMAX * 8)
#define BATCH 8
#define IDXMASK 0x1FFFFF

// ---------------- device scratch ----------------
__device__ float g_sum[C_IN];
__device__ float g_sq[C_IN];
__device__ float g_scale[C_IN];
__device__ float g_shift[C_IN];
__device__ int   g_hist2[NBINSMAX];
__device__ int   g_base2[NBINSMAX + 1];
__device__ int   g_cur2[NBINSMAX];
__device__ int   g_perm[NMAX];

// ---------------- PTX helpers ----------------
__device__ __forceinline__ unsigned long long fma2(unsigned long long a,
                                                   unsigned long long b,
                                                   unsigned long long c) {
    unsigned long long d;
    asm("fma.rn.f32x2 %0, %1, %2, %3;" : "=l"(d) : "l"(a), "l"(b), "l"(c));
    return d;
}
__device__ __forceinline__ unsigned long long pk(float lo, float hi) {
    unsigned long long d;
    asm("mov.b64 %0, {%1, %2};" : "=l"(d) : "f"(lo), "f"(hi));
    return d;
}
__device__ __forceinline__ void upk(unsigned long long v, float& lo, float& hi) {
    asm("mov.b64 {%0, %1}, %2;" : "=f"(lo), "=f"(hi) : "l"(v));
}
__device__ __forceinline__ void red_add_v2(float* p, float a, float b) {
    asm volatile("red.global.add.v2.f32 [%0], {%1, %2};"
                 :: "l"(p), "f"(a), "f"(b) : "memory");
}

// ---------------- BN stats + 2-D (bucket,tap) histogram (R5 exact) ----------------
// g_hist2 / g_sum / g_sq zero on entry (zero-init at load; re-zeroed by
// k_scanmid each call -> replay-safe).
__global__ void __launch_bounds__(256) k_pre(
    const float4* __restrict__ f4, long nf4,
    const int4* __restrict__ off4, const int4* __restrict__ oix4,
    int nq, int n) {
    long tid = blockIdx.x * (long)blockDim.x + threadIdx.x;
    long S = (long)gridDim.x * blockDim.x;   // 4*S % 32 == 0

    float s0 = 0, s1 = 0, s2 = 0, s3 = 0;
    float q0 = 0, q1 = 0, q2 = 0, q3 = 0;
    for (long i = tid; i < nf4; i += S) {
        float4 v = f4[i];
        s0 += v.x; q0 = fmaf(v.x, v.x, q0);
        s1 += v.y; q1 = fmaf(v.y, v.y, q1);
        s2 += v.z; q2 = fmaf(v.z, v.z, q2);
        s3 += v.w; q3 = fmaf(v.w, v.w, q3);
    }
    int c0 = (int)((tid * 4) & 31);

    __shared__ float ss[C_IN], sq[C_IN];
    int t = threadIdx.x;
    if (t < C_IN) { ss[t] = 0.f; sq[t] = 0.f; }
    __syncthreads();
    atomicAdd(&ss[c0 + 0], s0); atomicAdd(&sq[c0 + 0], q0);
    atomicAdd(&ss[c0 + 1], s1); atomicAdd(&sq[c0 + 1], q1);
    atomicAdd(&ss[c0 + 2], s2); atomicAdd(&sq[c0 + 2], q2);
    atomicAdd(&ss[c0 + 3], s3); atomicAdd(&sq[c0 + 3], q3);

    for (long i = tid; i < nq; i += S) {
        int4 o = off4[i];
        int4 r = oix4[i];
        atomicAdd(&g_hist2[((r.x >> BSHIFT) << 3) + (o.x & 7)], 1);
        atomicAdd(&g_hist2[((r.y >> BSHIFT) << 3) + (o.y & 7)], 1);
        atomicAdd(&g_hist2[((r.z >> BSHIFT) << 3) + (o.z & 7)], 1);
        atomicAdd(&g_hist2[((r.w >> BSHIFT) << 3) + (o.w & 7)], 1);
    }
    if (blockIdx.x == 0 && t < (n & 3)) {
        const int* off = (const int*)off4;
        const int* oix = (const int*)oix4;
        int e = (n & ~3) + t;
        atomicAdd(&g_hist2[((oix[e] >> BSHIFT) << 3) + (off[e] & 7)], 1);
    }
    __syncthreads();
    if (t < C_IN) {
        atomicAdd(&g_sum[t], ss[t]);
        atomicAdd(&g_sq[t], sq[t]);
    }
}

// ---------------- single-block: BN finalize + full bin scan + resets ----------------
__global__ void __launch_bounds__(1024) k_scanmid(
    const float* __restrict__ gamma, const float* __restrict__ beta,
    float inv_n, int nbins) {
    __shared__ int wtot[32];
    int t = threadIdx.x;
    int lane = t & 31, wid = t >> 5;

    if (t < C_IN) {
        float mean = g_sum[t] * inv_n;
        float var  = g_sq[t] * inv_n - mean * mean;
        float sc   = gamma[t] * rsqrtf(var + 1e-5f);
        g_scale[t] = sc;
        g_shift[t] = beta[t] - mean * sc;
        g_sum[t] = 0.f;
        g_sq[t]  = 0.f;
    }

    int b0 = t << 4;
    int h[16];
#pragma unroll
    for (int k = 0; k < 16; k++) {
        int b = b0 + k;
        h[k] = (b < nbins) ? g_hist2[b] : 0;
    }
    int s = 0;
#pragma unroll
    for (int k = 0; k < 16; k++) { int v = h[k]; h[k] = s; s += v; }

    int inc = s;
#pragma unroll
    for (int d = 1; d < 32; d <<= 1) {
        int u = __shfl_up_sync(FULLMASK, inc, d);
        if (lane >= d) inc += u;
    }
    if (lane == 31) wtot[wid] = inc;
    __syncthreads();
    if (wid == 0) {
        int x = wtot[lane];
#pragma unroll
        for (int d = 1; d < 32; d <<= 1) {
            int u = __shfl_up_sync(FULLMASK, x, d);
            if (lane >= d) x += u;
        }
        wtot[lane] = x;
    }
    __syncthreads();
    int base = (wid ? wtot[wid - 1] : 0) + inc - s;
#pragma unroll
    for (int k = 0; k < 16; k++) {
        int b = b0 + k;
        if (b < nbins) {
            int e = base + h[k];
            g_base2[b] = e;
            g_cur2[b] = e;
            g_hist2[b] = 0;
        }
    }
    if (t == 1023) g_base2[nbins] = base + s;
}

// ---------------- counting-sort scatter: packed (rowlow<<21 | idx) (R5 exact) ----------------
__global__ void k_scat(const int4* __restrict__ off4,
                       const int4* __restrict__ oix4, int nq, int n) {
    int i = blockIdx.x * blockDim.x + threadIdx.x;
    int S = gridDim.x * blockDim.x;
    for (; i < nq; i += S) {
        int4 o = off4[i];
        int4 r = oix4[i];
        int base = i << 2;
        {
            int pos = atomicAdd(&g_cur2[((r.x >> BSHIFT) << 3) + (o.x & 7)], 1);
            g_perm[pos] = ((r.x & (BROWS - 1)) << 21) | (base + 0);
        }
        {
            int pos = atomicAdd(&g_cur2[((r.y >> BSHIFT) << 3) + (o.y & 7)], 1);
            g_perm[pos] = ((r.y & (BROWS - 1)) << 21) | (base + 1);
        }
        {
            int pos = atomicAdd(&g_cur2[((r.z >> BSHIFT) << 3) + (o.z & 7)], 1);
            g_perm[pos] = ((r.z & (BROWS - 1)) << 21) | (base + 2);
        }
        {
            int pos = atomicAdd(&g_cur2[((r.w >> BSHIFT) << 3) + (o.w & 7)], 1);
            g_perm[pos] = ((r.w & (BROWS - 1)) << 21) | (base + 3);
        }
    }
    if (blockIdx.x == 0 && threadIdx.x < (n & 3)) {
        const int* off = (const int*)off4;
        const int* oix = (const int*)oix4;
        int e = (n & ~3) + threadIdx.x;
        int row = oix[e];
        int pos = atomicAdd(&g_cur2[((row >> BSHIFT) << 3) + (off[e] & 7)], 1);
        g_perm[pos] = ((row & (BROWS - 1)) << 21) | e;
    }
}

// ---------------- main conv (R5 verbatim): CTA-per-bucket, warp = tap, dist-2 ----------------
__global__ void __launch_bounds__(256, 2)
k_conv(const float* __restrict__ f, const float* __restrict__ weight,
       float* __restrict__ out, int nb, int nrows) {
    __shared__ float sv[8][2][BATCH][C_IN];
    int lane = threadIdx.x & 31;
    int wl = threadIdx.x >> 5;          // warp id == tap id

    // tap weights, channel-paired: w0[k] = {w[2k][2l], w[2k+1][2l]}, w1 for col 2l+1
    unsigned long long w0[16], w1[16];
    {
        const float* wp = weight + (wl * C_IN) * C_OUT;
#pragma unroll
        for (int k = 0; k < 16; k++) {
            w0[k] = pk(wp[(2 * k) * C_OUT + 2 * lane],
                       wp[(2 * k + 1) * C_OUT + 2 * lane]);
            w1[k] = pk(wp[(2 * k) * C_OUT + 2 * lane + 1],
                       wp[(2 * k + 1) * C_OUT + 2 * lane + 1]);
        }
    }
    float sc = g_scale[lane];
    float sh = g_shift[lane];

    for (int b = blockIdx.x; b < nb; b += gridDim.x) {
        // zero this bucket's output region (lines stay dirty in L2 for atomics)
        long r0 = (long)b << BSHIFT;
        long r1 = min((long)nrows, r0 + (long)BROWS);
        float4* oz = (float4*)(out + r0 * C_OUT);
        long n4 = (r1 - r0) * (C_OUT / 4);
        float4 z = make_float4(0.f, 0.f, 0.f, 0.f);
        for (long i = threadIdx.x; i < n4; i += 256) oz[i] = z;
        __syncthreads();

        int bin = (b << 3) + wl;
        int j = g_base2[bin];
        int j1 = g_base2[bin + 1];
        int rbase = b << BSHIFT;

        // ---- prologue: words(k), words(k+1), features(k) ----
        int m = min(BATCH, j1 - j);
        int wc[BATCH], wn[BATCH], wn2[BATCH];
        float x[BATCH];
#pragma unroll
        for (int t = 0; t < BATCH; t++)
            if (t < m) wc[t] = g_perm[j + t];
        int jn = j + m;
        int mn = min(BATCH, j1 - jn);
#pragma unroll
        for (int t = 0; t < BATCH; t++)
            if (t < mn) wn[t] = g_perm[jn + t];
#pragma unroll
        for (int t = 0; t < BATCH; t++)
            if (t < m) x[t] = f[((long)(wc[t] & IDXMASK) << 5) + lane];

        int it = 0;
        while (j < j1) {
            int buf = it & 1;
            // stage batch k (consumes x)
#pragma unroll
            for (int t = 0; t < BATCH; t++)
                if (t < m) sv[wl][buf][t][lane] = fmaxf(fmaf(x[t], sc, sh), 0.f);
            __syncwarp();

            // issue features(k+1) from resident words(k+1)
#pragma unroll
            for (int t = 0; t < BATCH; t++)
                if (t < mn) x[t] = f[((long)(wn[t] & IDXMASK) << 5) + lane];

            // issue words(k+2)
            int jn2 = jn + mn;
            int mn2 = min(BATCH, j1 - jn2);
#pragma unroll
            for (int t = 0; t < BATCH; t++)
                if (t < mn2) wn2[t] = g_perm[jn2 + t];

            // compute + reduce batch k
#pragma unroll
            for (int t = 0; t < BATCH; t++)
                if (t < m) {
                    const ulonglong2* vp = (const ulonglong2*)&sv[wl][buf][t][0];
                    unsigned long long a0 = 0ull, a1 = 0ull;
#pragma unroll
                    for (int k = 0; k < 8; k++) {
                        ulonglong2 q = vp[k];   // {v4k,v4k+1 | v4k+2,v4k+3} broadcast
                        a0 = fma2(q.x, w0[2 * k], a0);
                        a1 = fma2(q.x, w1[2 * k], a1);
                        a0 = fma2(q.y, w0[2 * k + 1], a0);
                        a1 = fma2(q.y, w1[2 * k + 1], a1);
                    }
                    float e0, o0, e1, o1;
                    upk(a0, e0, o0);
                    upk(a1, e1, o1);
                    int row = rbase + (wc[t] >> 21);
                    red_add_v2(out + ((long)row << 6) + (lane << 1),
                               e0 + o0, e1 + o1);
                }

            // rotate pipeline
#pragma unroll
            for (int t = 0; t < BATCH; t++) { wc[t] = wn[t]; wn[t] = wn2[t]; }
            j = jn; m = mn; jn = jn2; mn = mn2;
            it++;
        }
    }
}

// ---------------- launch ----------------
extern "C" void kernel_launch(void* const* d_in, const int* in_sizes, int n_in,
                              void* d_out, int out_size) {
    const float* features = (const float*)d_in[0];
    const float* gamma    = (const float*)d_in[1];
    const float* beta     = (const float*)d_in[2];
    const float* weight   = (const float*)d_in[3];
    const int* out_index  = (const int*)d_in[4];
    const int* off_index  = (const int*)d_in[5];

    int n = in_sizes[0] / C_IN;
    int nq = n >> 2;
    int nrows = out_size / C_OUT;
    int nb = (nrows + BROWS - 1) >> BSHIFT;
    int nbins = nb * 8;

    k_pre<<<592, 256>>>((const float4*)features, (long)n * C_IN / 4,
                        (const int4*)off_index, (const int4*)out_index, nq, n);
    k_scanmid<<<1, 1024>>>(gamma, beta, 1.0f / (float)n, nbins);
    k_scat<<<592, 256>>>((const int4*)off_index, (const int4*)out_index, nq, n);
    k_conv<<<296, 256>>>(features, weight, (float*)d_out, nb, nrows);
}

// round 16
// speedup vs baseline: 1.6743x; 1.0110x over previous
#include <cuda_runtime.h>

#define FULLMASK 0xffffffffu
#define C_IN 32
#define C_OUT 64
#define K_TAPS 8
#define NMAX 2001024
#define BSHIFT 10                    // 1024 output rows per bucket
#define BROWS (1 << BSHIFT)
#define NBMAX ((NMAX >> BSHIFT) + 2)
#define NBINSMAX (NBMAX * 8)
#define BATCH 8
#define IDXMASK 0x1FFFFF

// ---------------- device scratch ----------------
__device__ float g_sum[C_IN];
__device__ float g_sq[C_IN];
__device__ float g_scale[C_IN];
__device__ float g_shift[C_IN];
__device__ int   g_hist2[NBINSMAX];
__device__ int   g_base2[NBINSMAX + 1];
__device__ int   g_cur2[NBINSMAX];
__device__ int   g_perm[NMAX];

// ---------------- PTX helpers ----------------
__device__ __forceinline__ unsigned long long fma2(unsigned long long a,
                                                   unsigned long long b,
                                                   unsigned long long c) {
    unsigned long long d;
    asm("fma.rn.f32x2 %0, %1, %2, %3;" : "=l"(d) : "l"(a), "l"(b), "l"(c));
    return d;
}
__device__ __forceinline__ unsigned long long pk(float lo, float hi) {
    unsigned long long d;
    asm("mov.b64 %0, {%1, %2};" : "=l"(d) : "f"(lo), "f"(hi));
    return d;
}
__device__ __forceinline__ void upk(unsigned long long v, float& lo, float& hi) {
    asm("mov.b64 {%0, %1}, %2;" : "=f"(lo), "=f"(hi) : "l"(v));
}
__device__ __forceinline__ void red_add_v2(float* p, float a, float b) {
    asm volatile("red.global.add.v2.f32 [%0], {%1, %2};"
                 :: "l"(p), "f"(a), "f"(b) : "memory");
}

// ---------------- BN stats + 2-D (bucket,tap) histogram ----------------
// g_hist2 / g_sum / g_sq zero on entry (zero-init at load; re-zeroed by
// k_scanmid each call -> replay-safe). All input reads are evict-first (.cs).
__global__ void __launch_bounds__(256) k_pre(
    const float4* __restrict__ f4, long nf4,
    const int4* __restrict__ off4, const int4* __restrict__ oix4,
    int nq, int n) {
    long tid = blockIdx.x * (long)blockDim.x + threadIdx.x;
    long S = (long)gridDim.x * blockDim.x;   // 4*S % 32 == 0

    float s0 = 0, s1 = 0, s2 = 0, s3 = 0;
    float q0 = 0, q1 = 0, q2 = 0, q3 = 0;
    for (long i = tid; i < nf4; i += S) {
        float4 v = __ldcs(&f4[i]);
        s0 += v.x; q0 = fmaf(v.x, v.x, q0);
        s1 += v.y; q1 = fmaf(v.y, v.y, q1);
        s2 += v.z; q2 = fmaf(v.z, v.z, q2);
        s3 += v.w; q3 = fmaf(v.w, v.w, q3);
    }
    int c0 = (int)((tid * 4) & 31);

    __shared__ float ss[C_IN], sq[C_IN];
    int t = threadIdx.x;
    if (t < C_IN) { ss[t] = 0.f; sq[t] = 0.f; }
    __syncthreads();
    atomicAdd(&ss[c0 + 0], s0); atomicAdd(&sq[c0 + 0], q0);
    atomicAdd(&ss[c0 + 1], s1); atomicAdd(&sq[c0 + 1], q1);
    atomicAdd(&ss[c0 + 2], s2); atomicAdd(&sq[c0 + 2], q2);
    atomicAdd(&ss[c0 + 3], s3); atomicAdd(&sq[c0 + 3], q3);

    for (long i = tid; i < nq; i += S) {
        int4 o = __ldcs(&off4[i]);
        int4 r = __ldcs(&oix4[i]);
        atomicAdd(&g_hist2[((r.x >> BSHIFT) << 3) + (o.x & 7)], 1);
        atomicAdd(&g_hist2[((r.y >> BSHIFT) << 3) + (o.y & 7)], 1);
        atomicAdd(&g_hist2[((r.z >> BSHIFT) << 3) + (o.z & 7)], 1);
        atomicAdd(&g_hist2[((r.w >> BSHIFT) << 3) + (o.w & 7)], 1);
    }
    if (blockIdx.x == 0 && t < (n & 3)) {
        const int* off = (const int*)off4;
        const int* oix = (const int*)oix4;
        int e = (n & ~3) + t;
        atomicAdd(&g_hist2[((oix[e] >> BSHIFT) << 3) + (off[e] & 7)], 1);
    }
    __syncthreads();
    if (t < C_IN) {
        atomicAdd(&g_sum[t], ss[t]);
        atomicAdd(&g_sq[t], sq[t]);
    }
}

// ---------------- single-block: BN finalize + full bin scan + resets ----------------
__global__ void __launch_bounds__(1024) k_scanmid(
    const float* __restrict__ gamma, const float* __restrict__ beta,
    float inv_n, int nbins) {
    __shared__ int wtot[32];
    int t = threadIdx.x;
    int lane = t & 31, wid = t >> 5;

    if (t < C_IN) {
        float mean = g_sum[t] * inv_n;
        float var  = g_sq[t] * inv_n - mean * mean;
        float sc   = gamma[t] * rsqrtf(var + 1e-5f);
        g_scale[t] = sc;
        g_shift[t] = beta[t] - mean * sc;
        g_sum[t] = 0.f;
        g_sq[t]  = 0.f;
    }

    int b0 = t << 4;
    int h[16];
#pragma unroll
    for (int k = 0; k < 16; k++) {
        int b = b0 + k;
        h[k] = (b < nbins) ? g_hist2[b] : 0;
    }
    int s = 0;
#pragma unroll
    for (int k = 0; k < 16; k++) { int v = h[k]; h[k] = s; s += v; }

    int inc = s;
#pragma unroll
    for (int d = 1; d < 32; d <<= 1) {
        int u = __shfl_up_sync(FULLMASK, inc, d);
        if (lane >= d) inc += u;
    }
    if (lane == 31) wtot[wid] = inc;
    __syncthreads();
    if (wid == 0) {
        int x = wtot[lane];
#pragma unroll
        for (int d = 1; d < 32; d <<= 1) {
            int u = __shfl_up_sync(FULLMASK, x, d);
            if (lane >= d) x += u;
        }
        wtot[lane] = x;
    }
    __syncthreads();
    int base = (wid ? wtot[wid - 1] : 0) + inc - s;
#pragma unroll
    for (int k = 0; k < 16; k++) {
        int b = b0 + k;
        if (b < nbins) {
            int e = base + h[k];
            g_base2[b] = e;
            g_cur2[b] = e;
            g_hist2[b] = 0;
        }
    }
    if (t == 1023) g_base2[nbins] = base + s;
}

// ---------------- counting-sort scatter: packed (rowlow<<21 | idx) ----------------
__global__ void k_scat(const int4* __restrict__ off4,
                       const int4* __restrict__ oix4, int nq, int n) {
    int i = blockIdx.x * blockDim.x + threadIdx.x;
    int S = gridDim.x * blockDim.x;
    for (; i < nq; i += S) {
        int4 o = __ldcs(&off4[i]);
        int4 r = __ldcs(&oix4[i]);
        int base = i << 2;
        {
            int pos = atomicAdd(&g_cur2[((r.x >> BSHIFT) << 3) + (o.x & 7)], 1);
            g_perm[pos] = ((r.x & (BROWS - 1)) << 21) | (base + 0);
        }
        {
            int pos = atomicAdd(&g_cur2[((r.y >> BSHIFT) << 3) + (o.y & 7)], 1);
            g_perm[pos] = ((r.y & (BROWS - 1)) << 21) | (base + 1);
        }
        {
            int pos = atomicAdd(&g_cur2[((r.z >> BSHIFT) << 3) + (o.z & 7)], 1);
            g_perm[pos] = ((r.z & (BROWS - 1)) << 21) | (base + 2);
        }
        {
            int pos = atomicAdd(&g_cur2[((r.w >> BSHIFT) << 3) + (o.w & 7)], 1);
            g_perm[pos] = ((r.w & (BROWS - 1)) << 21) | (base + 3);
        }
    }
    if (blockIdx.x == 0 && threadIdx.x < (n & 3)) {
        const int* off = (const int*)off4;
        const int* oix = (const int*)oix4;
        int e = (n & ~3) + threadIdx.x;
        int row = oix[e];
        int pos = atomicAdd(&g_cur2[((row >> BSHIFT) << 3) + (off[e] & 7)], 1);
        g_perm[pos] = ((row & (BROWS - 1)) << 21) | e;
    }
}

// ---------------- main conv (R5 form + .cs streams): CTA-per-bucket, warp = tap ----------------
__global__ void __launch_bounds__(256, 2)
k_conv(const float* __restrict__ f, const float* __restrict__ weight,
       float* __restrict__ out, int nb, int nrows) {
    __shared__ float sv[8][2][BATCH][C_IN];
    int lane = threadIdx.x & 31;
    int wl = threadIdx.x >> 5;          // warp id == tap id

    // tap weights, channel-paired: w0[k] = {w[2k][2l], w[2k+1][2l]}, w1 for col 2l+1
    unsigned long long w0[16], w1[16];
    {
        const float* wp = weight + (wl * C_IN) * C_OUT;
#pragma unroll
        for (int k = 0; k < 16; k++) {
            w0[k] = pk(wp[(2 * k) * C_OUT + 2 * lane],
                       wp[(2 * k + 1) * C_OUT + 2 * lane]);
            w1[k] = pk(wp[(2 * k) * C_OUT + 2 * lane + 1],
                       wp[(2 * k + 1) * C_OUT + 2 * lane + 1]);
        }
    }
    float sc = g_scale[lane];
    float sh = g_shift[lane];

    for (int b = blockIdx.x; b < nb; b += gridDim.x) {
        // zero this bucket's output region (lines stay dirty in L2 for atomics)
        long r0 = (long)b << BSHIFT;
        long r1 = min((long)nrows, r0 + (long)BROWS);
        float4* oz = (float4*)(out + r0 * C_OUT);
        long n4 = (r1 - r0) * (C_OUT / 4);
        float4 z = make_float4(0.f, 0.f, 0.f, 0.f);
        for (long i = threadIdx.x; i < n4; i += 256) oz[i] = z;
        __syncthreads();

        int bin = (b << 3) + wl;
        int j = g_base2[bin];
        int j1 = g_base2[bin + 1];
        int rbase = b << BSHIFT;

        // ---- prologue: words(k), words(k+1), features(k) ----
        int m = min(BATCH, j1 - j);
        int wc[BATCH], wn[BATCH], wn2[BATCH];
        float x[BATCH];
#pragma unroll
        for (int t = 0; t < BATCH; t++)
            if (t < m) wc[t] = __ldcs(&g_perm[j + t]);
        int jn = j + m;
        int mn = min(BATCH, j1 - jn);
#pragma unroll
        for (int t = 0; t < BATCH; t++)
            if (t < mn) wn[t] = __ldcs(&g_perm[jn + t]);
#pragma unroll
        for (int t = 0; t < BATCH; t++)
            if (t < m) x[t] = __ldcs(&f[((long)(wc[t] & IDXMASK) << 5) + lane]);

        int it = 0;
        while (j < j1) {
            int buf = it & 1;
            // stage batch k (consumes x)
#pragma unroll
            for (int t = 0; t < BATCH; t++)
                if (t < m) sv[wl][buf][t][lane] = fmaxf(fmaf(x[t], sc, sh), 0.f);
            __syncwarp();

            // issue features(k+1) from resident words(k+1)
#pragma unroll
            for (int t = 0; t < BATCH; t++)
                if (t < mn) x[t] = __ldcs(&f[((long)(wn[t] & IDXMASK) << 5) + lane]);

            // issue words(k+2)
            int jn2 = jn + mn;
            int mn2 = min(BATCH, j1 - jn2);
#pragma unroll
            for (int t = 0; t < BATCH; t++)
                if (t < mn2) wn2[t] = __ldcs(&g_perm[jn2 + t]);

            // compute + reduce batch k
#pragma unroll
            for (int t = 0; t < BATCH; t++)
                if (t < m) {
                    const ulonglong2* vp = (const ulonglong2*)&sv[wl][buf][t][0];
                    unsigned long long a0 = 0ull, a1 = 0ull;
#pragma unroll
                    for (int k = 0; k < 8; k++) {
                        ulonglong2 q = vp[k];   // {v4k,v4k+1 | v4k+2,v4k+3} broadcast
                        a0 = fma2(q.x, w0[2 * k], a0);
                        a1 = fma2(q.x, w1[2 * k], a1);
                        a0 = fma2(q.y, w0[2 * k + 1], a0);
                        a1 = fma2(q.y, w1[2 * k + 1], a1);
                    }
                    float e0, o0, e1, o1;
                    upk(a0, e0, o0);
                    upk(a1, e1, o1);
                    int row = rbase + (wc[t] >> 21);
                    red_add_v2(out + ((long)row << 6) + (lane << 1),
                               e0 + o0, e1 + o1);
                }

            // rotate pipeline
#pragma unroll
            for (int t = 0; t < BATCH; t++) { wc[t] = wn[t]; wn[t] = wn2[t]; }
            j = jn; m = mn; jn = jn2; mn = mn2;
            it++;
        }
    }
}

// ---------------- launch ----------------
extern "C" void kernel_launch(void* const* d_in, const int* in_sizes, int n_in,
                              void* d_out, int out_size) {
    const float* features = (const float*)d_in[0];
    const float* gamma    = (const float*)d_in[1];
    const float* beta     = (const float*)d_in[2];
    const float* weight   = (const float*)d_in[3];
    const int* out_index  = (const int*)d_in[4];
    const int* off_index  = (const int*)d_in[5];

    int n = in_sizes[0] / C_IN;
    int nq = n >> 2;
    int nrows = out_size / C_OUT;
    int nb = (nrows + BROWS - 1) >> BSHIFT;
    int nbins = nb * 8;

    k_pre<<<592, 256>>>((const float4*)features, (long)n * C_IN / 4,
                        (const int4*)off_index, (const int4*)out_index, nq, n);
    k_scanmid<<<1, 1024>>>(gamma, beta, 1.0f / (float)n, nbins);
    k_scat<<<592, 256>>>((const int4*)off_index, (const int4*)out_index, nq, n);
    k_conv<<<296, 256>>>(features, weight, (float*)d_out, nb, nrows);
}